// round 10
// baseline (speedup 1.0000x reference)
#include <cuda_runtime.h>
#include <math.h>

#define N_ATOMS  4096
#define NRBF     16
#define NHID     64

#define NCELL1   8                       // cells per axis (BOX/CUTOFF = 40/5)
#define NCELLS   (NCELL1*NCELL1*NCELL1)  // 512
#define CELL_CAP 64                      // mean occupancy ~8
#define CAND_CAP 512                     // 27 cells * ~8 = ~216 expected
#define ACC_CAP  128                     // accepted neighbors: mean ~33
#define INV_CELL 0.2f                    // 1 / 5.0

// ---- scratch (no allocations allowed) ----
__device__ float4 g_pos4[N_ATOMS];
__device__ int    g_cell_cnt[NCELLS];
__device__ int    g_cell_atoms[NCELLS * CELL_CAP];
__device__ float  g_block_e[NCELLS];        // per-block (per-cell) energy partials
__device__ int    g_done;                   // last-block ticket (reset in build)

// 1/(2*eta^2), eta = 0.5*(5.0-0.5)/16 = 9/64 -> A = 2048/81
#define RBF_A        25.28395061728395f
#define PI_OVER_CUT  0.6283185307179586f    // pi / 5.0
#define CUT_SQ       25.0f

__device__ __forceinline__ int cell_of(float x, float y, float z)
{
    int cx = min(NCELL1 - 1, max(0, (int)(x * INV_CELL)));
    int cy = min(NCELL1 - 1, max(0, (int)(y * INV_CELL)));
    int cz = min(NCELL1 - 1, max(0, (int)(z * INV_CELL)));
    return (cz * NCELL1 + cy) * NCELL1 + cx;
}

// ============================================================
// Kernel 1: pack positions + build per-cell atom lists.
// 64 blocks x 256 threads; warp-per-cell ballot scan (proven R8).
// ============================================================
__global__ __launch_bounds__(256)
void build_kernel(const float* __restrict__ pos)
{
    __shared__ int s_ids[N_ATOMS];   // 16 KB

    const int tid  = threadIdx.x;
    const int warp = tid >> 5;
    const int lane = tid & 31;

    if (blockIdx.x == 0 && tid == 0) g_done = 0;   // replay-safe ticket reset

    for (int a = tid; a < N_ATOMS; a += 256) {
        float x = pos[3 * a], y = pos[3 * a + 1], z = pos[3 * a + 2];
        s_ids[a] = cell_of(x, y, z);
    }
    if (tid < 64) {
        int a = blockIdx.x * 64 + tid;
        g_pos4[a] = make_float4(pos[3 * a], pos[3 * a + 1], pos[3 * a + 2], 0.0f);
    }
    __syncthreads();

    const int cell = blockIdx.x * 8 + warp;
    const unsigned lt = (1u << lane) - 1u;
    int cnt = 0;
    int* dst = &g_cell_atoms[cell * CELL_CAP];

    #pragma unroll 4
    for (int b = 0; b < N_ATOMS; b += 32) {
        bool m = (s_ids[b + lane] == cell);
        unsigned bal = __ballot_sync(0xffffffffu, m);
        if (m) {
            int ofs = cnt + __popc(bal & lt);
            if (ofs < CELL_CAP) dst[ofs] = b + lane;
        }
        cnt += __popc(bal);
    }
    if (lane == 0) g_cell_cnt[cell] = min(cnt, CELL_CAP);
}

// ============================================================
__device__ __forceinline__ float silu_f(float a)
{
    return a / (1.0f + __expf(-a));
}

__device__ __forceinline__ void rbf_batch(float sq, const float* __restrict__ c,
                                          float* __restrict__ f)
{
    float d = sqrtf(sq);                          // sentinel sq=1e8 -> d=1e4
    float w = 0.5f + 0.5f * __cosf(d * PI_OVER_CUT);
    #pragma unroll
    for (int k = 0; k < NRBF; k++) {
        float tt = d - c[k];
        float g  = __expf(-RBF_A * tt * tt);      // sentinel -> underflow to 0
        f[k] = fmaf(w, g, f[k]);
    }
}

// ============================================================
// Kernel 2: ONE BLOCK PER CELL. Candidate positions from the 27
// neighbor cells are staged into shared ONCE per block; each warp
// then processes one own-cell atom per pass (filter via LDS,
// compact, dense RBF, fused MLP). Block partial -> last-block sum.
// ============================================================
__global__ __launch_bounds__(256)
void gather_kernel(const float* __restrict__ centers,
                   const float* __restrict__ W1, const float* __restrict__ b1,
                   const float* __restrict__ W2, const float* __restrict__ b2,
                   const float* __restrict__ W3, const float* __restrict__ b3,
                   float* __restrict__ out)
{
    __shared__ float4 s_pos[CAND_CAP];      // 8 KB candidate positions
    __shared__ float  s_acc[8][ACC_CAP];    // 4 KB accepted sq per warp
    __shared__ float  s_h1[8][NHID];        // 2 KB hidden activations
    __shared__ int    s_ccell[27], s_ccnt[27], s_coff[27];
    __shared__ int    s_nc;
    __shared__ float  s_e[8];
    __shared__ int    s_last;
    __shared__ float  s_red[256];

    const int tid  = threadIdx.x;
    const int warp = tid >> 5;
    const int lane = tid & 31;
    const int cell = blockIdx.x;
    const unsigned FULL = 0xffffffffu;
    const unsigned lt   = (1u << lane) - 1u;

    const int cx = cell & 7;
    const int cy = (cell >> 3) & 7;
    const int cz = cell >> 6;

    // ---- warp 0: census of 27 neighbor cells + prefix offsets ----
    if (warp == 0) {
        int cellc = 0, cntc = 0;
        if (lane < 27) {
            int dz = lane / 9 - 1, r = lane % 9;
            int dy = r / 3 - 1,    dx = r % 3 - 1;
            int x = cx + dx, y = cy + dy, z = cz + dz;
            if (x >= 0 && x < NCELL1 && y >= 0 && y < NCELL1 && z >= 0 && z < NCELL1) {
                cellc = (z * NCELL1 + y) * NCELL1 + x;
                cntc  = g_cell_cnt[cellc];
            }
        }
        int pre = cntc;
        #pragma unroll
        for (int d = 1; d < 32; d <<= 1) {
            int n = __shfl_up_sync(FULL, pre, d);
            if (lane >= d) pre += n;
        }
        int off = pre - cntc;
        if (lane < 27) {
            int ce = min(cntc, max(0, CAND_CAP - off));  // clamp to capacity
            s_ccell[lane] = cellc;
            s_ccnt[lane]  = ce;
            s_coff[lane]  = off;
        }
        if (lane == 31) s_nc = min(pre, CAND_CAP);
    }
    __syncthreads();

    // ---- block-cooperative candidate position staging (once per block) ----
    for (int cI = warp; cI < 27; cI += 8) {
        int cnt_b  = s_ccnt[cI];
        if (cnt_b == 0) continue;
        int off_b  = s_coff[cI];
        const int* ca = &g_cell_atoms[s_ccell[cI] * CELL_CAP];
        if (lane < cnt_b)      s_pos[off_b + lane]      = g_pos4[ca[lane]];
        if (lane + 32 < cnt_b) s_pos[off_b + 32 + lane] = g_pos4[ca[lane + 32]];
    }
    __syncthreads();

    const int nc   = s_nc;
    const int ownN = s_ccnt[13];        // center cell (dx=dy=dz=0)
    const int ownO = s_coff[13];

    float c[NRBF];
    #pragma unroll
    for (int k = 0; k < NRBF; k++) c[k] = __ldg(&centers[k]);

    float e_warp = 0.0f;

    // ---- each warp: one own-cell atom per pass ----
    for (int a = warp; a < ownN; a += 8) {
        const float4 pi = s_pos[ownO + a];

        // filter pass over shared candidates (LDS, conflict-free)
        int acc = 0;
        const int iters = (nc + 31) >> 5;
        for (int it = 0; it < iters; it++) {
            int idx = (it << 5) + lane;
            float4 pj = (idx < nc) ? s_pos[idx]
                                   : make_float4(pi.x, pi.y, pi.z, 0.0f);
            float dx = pi.x - pj.x;
            float dy = pi.y - pj.y;
            float dz = pi.z - pj.z;
            float sq = fmaf(dx, dx, fmaf(dy, dy, dz * dz));
            bool ok  = (sq > 0.0f) && (sq < CUT_SQ);     // excludes self exactly
            unsigned m = __ballot_sync(FULL, ok);
            if (ok) {
                int ofs = acc + __popc(m & lt);
                if (ofs < ACC_CAP) s_acc[warp][ofs] = sq;
            }
            acc += __popc(m);
        }
        acc = min(acc, ACC_CAP);
        __syncwarp();

        // dense RBF over accepted pairs (~1-2 batches)
        float f[NRBF];
        #pragma unroll
        for (int k = 0; k < NRBF; k++) f[k] = 0.0f;
        for (int b = 0; b < acc; b += 32) {
            float sqv = (b + lane < acc) ? s_acc[warp][b + lane] : 1e8f;
            rbf_batch(sqv, c, f);
        }

        // butterfly-reduce: every lane gets the full feature vector
        #pragma unroll
        for (int off = 16; off > 0; off >>= 1) {
            #pragma unroll
            for (int k = 0; k < NRBF; k++)
                f[k] += __shfl_xor_sync(FULL, f[k], off);
        }

        // MLP, 2 hidden units per lane
        const int t0 = lane, t1 = lane + 32;
        float a0 = __ldg(&b1[t0]);
        float a1 = __ldg(&b1[t1]);
        #pragma unroll
        for (int k = 0; k < NRBF; k++) {
            a0 = fmaf(f[k], __ldg(&W1[k * NHID + t0]), a0);
            a1 = fmaf(f[k], __ldg(&W1[k * NHID + t1]), a1);
        }
        s_h1[warp][t0] = silu_f(a0);
        s_h1[warp][t1] = silu_f(a1);
        __syncwarp();

        float a2 = __ldg(&b2[t0]);
        float a3 = __ldg(&b2[t1]);
        #pragma unroll
        for (int u = 0; u < NHID; u += 4) {
            float4 hv = *reinterpret_cast<const float4*>(&s_h1[warp][u]);
            a2 = fmaf(hv.x, __ldg(&W2[(u + 0) * NHID + t0]), a2);
            a2 = fmaf(hv.y, __ldg(&W2[(u + 1) * NHID + t0]), a2);
            a2 = fmaf(hv.z, __ldg(&W2[(u + 2) * NHID + t0]), a2);
            a2 = fmaf(hv.w, __ldg(&W2[(u + 3) * NHID + t0]), a2);
            a3 = fmaf(hv.x, __ldg(&W2[(u + 0) * NHID + t1]), a3);
            a3 = fmaf(hv.y, __ldg(&W2[(u + 1) * NHID + t1]), a3);
            a3 = fmaf(hv.z, __ldg(&W2[(u + 2) * NHID + t1]), a3);
            a3 = fmaf(hv.w, __ldg(&W2[(u + 3) * NHID + t1]), a3);
        }
        __syncwarp();   // s_h1 reuse across passes

        float v = silu_f(a2) * __ldg(&W3[t0]) + silu_f(a3) * __ldg(&W3[t1]);
        #pragma unroll
        for (int off = 16; off > 0; off >>= 1)
            v += __shfl_down_sync(FULL, v, off);
        if (lane == 0) e_warp += v + __ldg(&b3[0]);
        e_warp = __shfl_sync(FULL, e_warp, 0);   // keep warp-uniform
    }

    if (lane == 0) s_e[warp] = e_warp;
    __syncthreads();

    // ---- block partial + last-block deterministic reduction ----
    if (tid == 0) {
        float be = 0.0f;
        #pragma unroll
        for (int w = 0; w < 8; w++) be += s_e[w];   // fixed warp order
        g_block_e[blockIdx.x] = be;
        __threadfence();
        int t = atomicAdd(&g_done, 1);
        s_last = (t == gridDim.x - 1);
    }
    __syncthreads();

    if (s_last) {
        float v2 = g_block_e[tid] + g_block_e[tid + 256];  // fixed order
        s_red[tid] = v2;
        __syncthreads();
        #pragma unroll
        for (int s = 128; s > 0; s >>= 1) {
            if (tid < s) s_red[tid] += s_red[tid + s];
            __syncthreads();
        }
        if (tid == 0) out[0] = s_red[0];
    }
}

// ============================================================
extern "C" void kernel_launch(void* const* d_in, const int* in_sizes, int n_in,
                              void* d_out, int out_size)
{
    const float* pos     = (const float*)d_in[0];
    const float* centers = (const float*)d_in[1];
    const float* W1      = (const float*)d_in[2];
    const float* b1      = (const float*)d_in[3];
    const float* W2      = (const float*)d_in[4];
    const float* b2      = (const float*)d_in[5];
    const float* W3      = (const float*)d_in[6];
    const float* b3      = (const float*)d_in[7];

    build_kernel<<<NCELLS / 8, 256>>>(pos);
    gather_kernel<<<NCELLS, 256>>>(centers, W1, b1, W2, b2, W3, b3,
                                   (float*)d_out);
}